// round 10
// baseline (speedup 1.0000x reference)
#include <cuda_runtime.h>
#include <cstdint>

// Shapes fixed by the problem: B=16384, S=512, F=4, E=8, heads=2, Dh=4, H=16
#define FULLMASK 0xFFFFFFFFu
typedef unsigned long long ull;   // packed f32x2 (lo, hi) in an aligned reg pair

__device__ __forceinline__ ull pk2(float a, float b) {
    ull r; asm("mov.b64 %0, {%1, %2};" : "=l"(r) : "f"(a), "f"(b)); return r;
}
__device__ __forceinline__ void upk2(ull v, float& a, float& b) {
    asm("mov.b64 {%0, %1}, %2;" : "=f"(a), "=f"(b) : "l"(v));
}
__device__ __forceinline__ ull fma2(ull a, ull b, ull c) {
    ull d; asm("fma.rn.f32x2 %0, %1, %2, %3;" : "=l"(d) : "l"(a), "l"(b), "l"(c)); return d;
}
__device__ __forceinline__ ull add2(ull a, ull b) {
    ull d; asm("add.rn.f32x2 %0, %1, %2;" : "=l"(d) : "l"(a), "l"(b)); return d;
}

// Batch-invariant constants:
// [0:64)    wfold[p][i]       (folded q/k cross-attn scores)
// [64:72)   bfold[p]
// [72:136)  wv  = ca_w_in rows 16..23   ([j][i])
// [136:200) wo  = ca_w_out              ([e][j])
// [200:208) b_eff[e] = ca_b_out + W_out * bv
__device__ float g_all[208];
__constant__ __align__(16) float c_all[208];

// ---------------------------------------------------------------------------
// Pre-kernel: self-attention over Q (batch invariant) + fold cross-attn q/k.
// ---------------------------------------------------------------------------
__global__ void precompute_kernel(const float* __restrict__ Q,
                                  const float* __restrict__ sa_w_in,
                                  const float* __restrict__ sa_b_in,
                                  const float* __restrict__ sa_w_out,
                                  const float* __restrict__ sa_b_out,
                                  const float* __restrict__ ca_w_in,
                                  const float* __restrict__ ca_b_in,
                                  const float* __restrict__ ca_w_out,
                                  const float* __restrict__ ca_b_out)
{
    if (threadIdx.x != 0) return;

    float qh[4][8], kh[4][8], vh[4][8];
    for (int f = 0; f < 4; f++)
        for (int j = 0; j < 8; j++) {
            float aq = sa_b_in[j], ak = sa_b_in[8 + j], av = sa_b_in[16 + j];
            for (int i = 0; i < 8; i++) {
                float xi = Q[f * 8 + i];
                aq += xi * sa_w_in[j * 8 + i];
                ak += xi * sa_w_in[(8 + j) * 8 + i];
                av += xi * sa_w_in[(16 + j) * 8 + i];
            }
            qh[f][j] = aq; kh[f][j] = ak; vh[f][j] = av;
        }

    float ctx[4][8];
    for (int h = 0; h < 2; h++)
        for (int l = 0; l < 4; l++) {
            float sc[4], mx = -1e30f;
            for (int m = 0; m < 4; m++) {
                float s = 0.f;
                for (int d = 0; d < 4; d++) s += qh[l][h * 4 + d] * kh[m][h * 4 + d];
                sc[m] = s * 0.5f;
                mx = fmaxf(mx, sc[m]);
            }
            float den = 0.f;
            for (int m = 0; m < 4; m++) { sc[m] = expf(sc[m] - mx); den += sc[m]; }
            for (int d = 0; d < 4; d++) {
                float a = 0.f;
                for (int m = 0; m < 4; m++) a += sc[m] * vh[m][h * 4 + d];
                ctx[l][h * 4 + d] = a / den;
            }
        }

    float qupd[4][8];
    for (int f = 0; f < 4; f++)
        for (int e = 0; e < 8; e++) {
            float a = sa_b_out[e];
            for (int j = 0; j < 8; j++) a += ctx[f][j] * sa_w_out[e * 8 + j];
            qupd[f][e] = a;
        }

    float qc[4][8];
    for (int f = 0; f < 4; f++)
        for (int j = 0; j < 8; j++) {
            float a = ca_b_in[j];
            for (int e = 0; e < 8; e++) a += qupd[f][e] * ca_w_in[j * 8 + e];
            qc[f][j] = 0.5f * a;
        }

    for (int h = 0; h < 2; h++)
        for (int f = 0; f < 4; f++) {
            int p = h * 4 + f;
            for (int i = 0; i < 8; i++) {
                float w = 0.f;
                for (int d = 0; d < 4; d++)
                    w += qc[f][h * 4 + d] * ca_w_in[(8 + h * 4 + d) * 8 + i];
                g_all[p * 8 + i] = w;
            }
            float bf = 0.f;
            for (int d = 0; d < 4; d++) bf += qc[f][h * 4 + d] * ca_b_in[8 + h * 4 + d];
            g_all[64 + p] = bf;
        }

    // pack cross-attn v/out weights + effective bias
    for (int k = 0; k < 64; k++) g_all[72 + k]  = ca_w_in[128 + k];   // wv rows 16..23
    for (int k = 0; k < 64; k++) g_all[136 + k] = ca_w_out[k];
    for (int e = 0; e < 8; e++) {
        float be = ca_b_out[e];
        for (int j = 0; j < 8; j++) be += ca_w_out[e * 8 + j] * ca_b_in[16 + j];
        g_all[200 + e] = be;
    }
}

// ---------------------------------------------------------------------------
// Halving-exchange warp reductions. After return, lane holds fully-reduced
// value(s); for N<=32 index = lane >> log2(32/N).
// ---------------------------------------------------------------------------
template <int N>
__device__ __forceinline__ void warp_fold_reduce(float* V, int lane) {
    int c = N;
#pragma unroll
    for (int o = 16; o >= 1; o >>= 1) {
        if (c > 1) {
            int half = c >> 1;
#pragma unroll
            for (int j = 0; j < half; j++) {
                float send = (lane & o) ? V[j] : V[j + half];
                float recv = __shfl_xor_sync(FULLMASK, send, o);
                V[j] = ((lane & o) ? V[j + half] : V[j]) + recv;
            }
            c = half;
        } else {
            V[0] += __shfl_xor_sync(FULLMASK, V[0], o);
        }
    }
}

template <int N>
__device__ __forceinline__ void warp_fold_reduce2(ull* V, int lane) {
    int c = N;
#pragma unroll
    for (int o = 16; o >= 1; o >>= 1) {
        if (c > 1) {
            int half = c >> 1;
#pragma unroll
            for (int j = 0; j < half; j++) {
                ull send = (lane & o) ? V[j] : V[j + half];
                ull recv = __shfl_xor_sync(FULLMASK, send, o);
                V[j] = add2((lane & o) ? V[j + half] : V[j], recv);
            }
            c = half;
        } else {
            V[0] = add2(V[0], __shfl_xor_sync(FULLMASK, V[0], o));
        }
    }
}

// ---------------------------------------------------------------------------
// Main kernel: one CTA per batch element. 64 threads, 8 tokens per thread.
// x is STREAMED from L1/L2 in each compute chunk (4 passes total) instead of
// pinned in registers — cuts regs ~96 -> ~75 so 12 CTAs/SM fit, giving the
// scheduler enough warps to hide SHFL-chain and LDG latency.
// ---------------------------------------------------------------------------
__global__ void __launch_bounds__(64, 12)
afs_main_kernel(const float* __restrict__ x,
                const float* __restrict__ r_w1, const float* __restrict__ r_b1,
                const float* __restrict__ r_w2, const float* __restrict__ r_b2,
                float* __restrict__ out_head, float* __restrict__ out_sim)
{
    const int b = blockIdx.x;
    const int tid = threadIdx.x;
    const int lane = tid & 31;
    const int wid = tid >> 5;

    __shared__ __align__(16) float redA[2][64];   // per-warp A partials
    __shared__ float redS[2][8];                  // per-warp exp-sum partials
    __shared__ __align__(16) float redF[2][32];   // per-warp final-factor partials
    __shared__ float redD[2][4];                  // per-warp sim exp-sum partials
    __shared__ __align__(16) float sQ[32];        // Q_cross [f][e]

    const float4* X4 = reinterpret_cast<const float4*>(x + (size_t)b * 4096);
    const ull* cw2 = reinterpret_cast<const ull*>(c_all);   // [p*4+h] pairs

    // --- phase 1: scores -> exp -> A partials; p in 2 chunks of 4 ---
#pragma unroll
    for (int c = 0; c < 2; c++) {
        ull A2[16];                                // [pp*4+h]
#pragma unroll
        for (int j = 0; j < 16; j++) A2[j] = 0ull;
        float sums[4] = {0.f, 0.f, 0.f, 0.f};

#pragma unroll
        for (int t = 0; t < 8; t++) {
            float4 u0 = __ldca(&X4[(tid + 64 * t) * 2]);
            float4 u1 = __ldca(&X4[(tid + 64 * t) * 2 + 1]);
            ull xt[4];
            xt[0] = pk2(u0.x, u0.y); xt[1] = pk2(u0.z, u0.w);
            xt[2] = pk2(u1.x, u1.y); xt[3] = pk2(u1.z, u1.w);
#pragma unroll
            for (int pp = 0; pp < 4; pp++) {
                int p = 4 * c + pp;
                ull acc = fma2(cw2[p * 4 + 0], xt[0],
                          fma2(cw2[p * 4 + 1], xt[1],
                          fma2(cw2[p * 4 + 2], xt[2],
                          fma2(cw2[p * 4 + 3], xt[3], 0ull))));
                float slo, shi; upk2(acc, slo, shi);
                float e = __expf(slo + shi + c_all[64 + p]);
                sums[pp] += e;
                ull e2 = pk2(e, e);
#pragma unroll
                for (int h = 0; h < 4; h++)
                    A2[pp * 4 + h] = fma2(e2, xt[h], A2[pp * 4 + h]);
            }
        }

        warp_fold_reduce2<16>(A2, lane);           // lane holds packed idx lane>>1
        if (!(lane & 1))
            reinterpret_cast<ull*>(&redA[wid][32 * c])[lane >> 1] = A2[0];

        warp_fold_reduce<4>(sums, lane);           // lane holds idx lane>>3
        if (!(lane & 7)) redS[wid][4 * c + (lane >> 3)] = sums[0];
    }

    __syncthreads();

    // --- warp 0: ctx + Q_cross (constant-bank weights, no L1 traffic) ---
    if (wid == 0) {
        int f = lane >> 3, j = lane & 7;       // lane <-> (f, j)
        int h = j >> 2, p = h * 4 + f;
        float At[8];
#pragma unroll
        for (int i = 0; i < 8; i++) At[i] = 0.f;
        float den = 0.f;
#pragma unroll
        for (int w = 0; w < 2; w++) {
            const float4* r4 = reinterpret_cast<const float4*>(&redA[w][p * 8]);
            float4 v0 = r4[0], v1 = r4[1];
            At[0] += v0.x; At[1] += v0.y; At[2] += v0.z; At[3] += v0.w;
            At[4] += v1.x; At[5] += v1.y; At[6] += v1.z; At[7] += v1.w;
            den += redS[w][p];
        }

        float accv = 0.f;
#pragma unroll
        for (int i = 0; i < 8; i++) accv = fmaf(c_all[72 + j * 8 + i], At[i], accv);
        float ctxv = accv / den;                 // v bias folded into b_eff

        float q = c_all[200 + j];                // b_eff[e=j]
#pragma unroll
        for (int jj = 0; jj < 8; jj++) {
            float cv = __shfl_sync(FULLMASK, ctxv, f * 8 + jj);
            q = fmaf(c_all[136 + j * 8 + jj], cv, q);
        }
        sQ[f * 8 + j] = q;
    }
    __syncthreads();

    // --- phase 2: similarity (raw out), exp, FF + denom; f in 2 chunks of 2 ---
    const ull* sQ2 = reinterpret_cast<const ull*>(sQ);   // [f*4+h]
    float* simbase = out_sim + (size_t)b * 2048;
#pragma unroll
    for (int c = 0; c < 2; c++) {
        ull qv[8];                                       // sQ pairs for 2 f's
#pragma unroll
        for (int k = 0; k < 8; k++) qv[k] = sQ2[8 * c + k];

        ull FF2[8];                                      // [ff*4+h]
#pragma unroll
        for (int j = 0; j < 8; j++) FF2[j] = 0ull;
        float ds[2] = {0.f, 0.f};

#pragma unroll
        for (int t = 0; t < 8; t++) {
            float4 u0 = __ldca(&X4[(tid + 64 * t) * 2]);
            float4 u1 = __ldca(&X4[(tid + 64 * t) * 2 + 1]);
            ull xt[4];
            xt[0] = pk2(u0.x, u0.y); xt[1] = pk2(u0.z, u0.w);
            xt[2] = pk2(u1.x, u1.y); xt[3] = pk2(u1.z, u1.w);
#pragma unroll
            for (int ff = 0; ff < 2; ff++) {
                int f = 2 * c + ff;
                ull acc = fma2(qv[ff * 4 + 0], xt[0],
                          fma2(qv[ff * 4 + 1], xt[1],
                          fma2(qv[ff * 4 + 2], xt[2],
                          fma2(qv[ff * 4 + 3], xt[3], 0ull))));
                float slo, shi; upk2(acc, slo, shi);
                float s = slo + shi;
                __stcs(&simbase[f * 512 + tid + 64 * t], s);   // pre-softmax sim
                float e = __expf(s);
                ds[ff] += e;
                ull e2 = pk2(e, e);
#pragma unroll
                for (int h = 0; h < 4; h++)
                    FF2[ff * 4 + h] = fma2(e2, xt[h], FF2[ff * 4 + h]);
            }
        }

        warp_fold_reduce2<8>(FF2, lane);                 // lane holds packed idx lane>>2
        if (!(lane & 3))
            reinterpret_cast<ull*>(&redF[wid][16 * c])[lane >> 2] = FF2[0];

        warp_fold_reduce<2>(ds, lane);                   // lane holds idx lane>>4
        if (!(lane & 15)) redD[wid][2 * c + (lane >> 4)] = ds[0];
    }

    __syncthreads();

    // --- warp 0: normalize final factors + regression head (coalesced) ---
    if (wid == 0) {
        float s = 0.f;
#pragma unroll
        for (int w = 0; w < 2; w++) s += redF[w][lane];
        int f = lane >> 3;
        float den = 0.f;
#pragma unroll
        for (int w = 0; w < 2; w++) den += redD[w][f];
        float fused = s / den;          // lane k holds fused[k], k = f*8+e

        // hp[h] = r_w1[h][lane] * fused[lane]; coalesced loads, then fold<16>
        float hp[16];
#pragma unroll
        for (int h = 0; h < 16; h++)
            hp[h] = r_w1[h * 32 + lane] * fused;
        warp_fold_reduce<16>(hp, lane);          // lane holds h = lane>>1

        int h = lane >> 1;
        float hv = fmaxf(hp[0] + r_b1[h], 0.f);
        float o = (lane & 1) ? 0.f : hv * r_w2[h];
#pragma unroll
        for (int off = 16; off >= 1; off >>= 1)
            o += __shfl_xor_sync(FULLMASK, o, off);
        if (lane == 0) out_head[b] = o + r_b2[0];
    }
}

// ---------------------------------------------------------------------------
extern "C" void kernel_launch(void* const* d_in, const int* in_sizes, int n_in,
                              void* d_out, int out_size)
{
    const float* x        = (const float*)d_in[0];
    const float* Q        = (const float*)d_in[1];
    const float* sa_w_in  = (const float*)d_in[2];
    const float* sa_b_in  = (const float*)d_in[3];
    const float* sa_w_out = (const float*)d_in[4];
    const float* sa_b_out = (const float*)d_in[5];
    const float* ca_w_in  = (const float*)d_in[6];
    const float* ca_b_in  = (const float*)d_in[7];
    const float* ca_w_out = (const float*)d_in[8];
    const float* ca_b_out = (const float*)d_in[9];
    const float* r_w1     = (const float*)d_in[10];
    const float* r_b1     = (const float*)d_in[11];
    const float* r_w2     = (const float*)d_in[12];
    const float* r_b2     = (const float*)d_in[13];

    int B = in_sizes[0] / (512 * 8);

    float* out = (float*)d_out;
    float* out_head = out;       // (out, similarity) tuple order: out first
    float* out_sim  = out + B;   // then [B, 4, 512] similarity

    precompute_kernel<<<1, 32>>>(Q, sa_w_in, sa_b_in, sa_w_out, sa_b_out,
                                 ca_w_in, ca_b_in, ca_w_out, ca_b_out);

    // copy all folded/packed batch-invariant weights into the constant bank
    void* pAll = nullptr;
    cudaGetSymbolAddress(&pAll, g_all);
    cudaMemcpyToSymbolAsync(c_all, pAll, 208 * sizeof(float), 0,
                            cudaMemcpyDeviceToDevice, 0);

    afs_main_kernel<<<B, 64>>>(x, r_w1, r_b1, r_w2, r_b2, out_head, out_sim);
}

// round 11
// speedup vs baseline: 1.5269x; 1.5269x over previous
#include <cuda_runtime.h>
#include <cstdint>

// Shapes fixed by the problem: B=16384, S=512, F=4, E=8, heads=2, Dh=4, H=16
#define FULLMASK 0xFFFFFFFFu
typedef unsigned long long ull;   // packed f32x2 (lo, hi) in an aligned reg pair

__device__ __forceinline__ ull pk2(float a, float b) {
    ull r; asm("mov.b64 %0, {%1, %2};" : "=l"(r) : "f"(a), "f"(b)); return r;
}
__device__ __forceinline__ void upk2(ull v, float& a, float& b) {
    asm("mov.b64 {%0, %1}, %2;" : "=f"(a), "=f"(b) : "l"(v));
}
__device__ __forceinline__ ull fma2(ull a, ull b, ull c) {
    ull d; asm("fma.rn.f32x2 %0, %1, %2, %3;" : "=l"(d) : "l"(a), "l"(b), "l"(c)); return d;
}
__device__ __forceinline__ ull add2(ull a, ull b) {
    ull d; asm("add.rn.f32x2 %0, %1, %2;" : "=l"(d) : "l"(a), "l"(b)); return d;
}
__device__ __forceinline__ float ex2(float s) {
    float e; asm("ex2.approx.f32 %0, %1;" : "=f"(e) : "f"(s)); return e;
}

// Batch-invariant constants (all exp-folded weights pre-scaled by log2(e)):
// [0:64)    wfold'[p][i]  = wfold * log2e
// [64:80)   bias pairs    = (bfold'[p], 0) as ull at c2[32+p]
// [80:144)  wv  = ca_w_in rows 16..23   ([j][i])
// [144:208) wo  = ca_w_out              ([e][j])
// [208:216) b_eff[e] = ca_b_out + W_out * bv
__device__ float g_all[216];
__constant__ __align__(16) float c_all[216];

// ---------------------------------------------------------------------------
// Pre-kernel: self-attention over Q (batch invariant) + fold cross-attn q/k.
// ---------------------------------------------------------------------------
__global__ void precompute_kernel(const float* __restrict__ Q,
                                  const float* __restrict__ sa_w_in,
                                  const float* __restrict__ sa_b_in,
                                  const float* __restrict__ sa_w_out,
                                  const float* __restrict__ sa_b_out,
                                  const float* __restrict__ ca_w_in,
                                  const float* __restrict__ ca_b_in,
                                  const float* __restrict__ ca_w_out,
                                  const float* __restrict__ ca_b_out)
{
    if (threadIdx.x != 0) return;
    const float LOG2E = 1.4426950408889634f;

    float qh[4][8], kh[4][8], vh[4][8];
    for (int f = 0; f < 4; f++)
        for (int j = 0; j < 8; j++) {
            float aq = sa_b_in[j], ak = sa_b_in[8 + j], av = sa_b_in[16 + j];
            for (int i = 0; i < 8; i++) {
                float xi = Q[f * 8 + i];
                aq += xi * sa_w_in[j * 8 + i];
                ak += xi * sa_w_in[(8 + j) * 8 + i];
                av += xi * sa_w_in[(16 + j) * 8 + i];
            }
            qh[f][j] = aq; kh[f][j] = ak; vh[f][j] = av;
        }

    float ctx[4][8];
    for (int h = 0; h < 2; h++)
        for (int l = 0; l < 4; l++) {
            float sc[4], mx = -1e30f;
            for (int m = 0; m < 4; m++) {
                float s = 0.f;
                for (int d = 0; d < 4; d++) s += qh[l][h * 4 + d] * kh[m][h * 4 + d];
                sc[m] = s * 0.5f;
                mx = fmaxf(mx, sc[m]);
            }
            float den = 0.f;
            for (int m = 0; m < 4; m++) { sc[m] = expf(sc[m] - mx); den += sc[m]; }
            for (int d = 0; d < 4; d++) {
                float a = 0.f;
                for (int m = 0; m < 4; m++) a += sc[m] * vh[m][h * 4 + d];
                ctx[l][h * 4 + d] = a / den;
            }
        }

    float qupd[4][8];
    for (int f = 0; f < 4; f++)
        for (int e = 0; e < 8; e++) {
            float a = sa_b_out[e];
            for (int j = 0; j < 8; j++) a += ctx[f][j] * sa_w_out[e * 8 + j];
            qupd[f][e] = a;
        }

    float qc[4][8];
    for (int f = 0; f < 4; f++)
        for (int j = 0; j < 8; j++) {
            float a = ca_b_in[j];
            for (int e = 0; e < 8; e++) a += qupd[f][e] * ca_w_in[j * 8 + e];
            qc[f][j] = 0.5f * a;
        }

    for (int h = 0; h < 2; h++)
        for (int f = 0; f < 4; f++) {
            int p = h * 4 + f;
            for (int i = 0; i < 8; i++) {
                float w = 0.f;
                for (int d = 0; d < 4; d++)
                    w += qc[f][h * 4 + d] * ca_w_in[(8 + h * 4 + d) * 8 + i];
                g_all[p * 8 + i] = w * LOG2E;          // exp -> ex2 folding
            }
            float bf = 0.f;
            for (int d = 0; d < 4; d++) bf += qc[f][h * 4 + d] * ca_b_in[8 + h * 4 + d];
            g_all[64 + 2 * p]     = bf * LOG2E;        // (b', 0) ull pair
            g_all[64 + 2 * p + 1] = 0.f;
        }

    // pack cross-attn v/out weights + effective bias
    for (int k = 0; k < 64; k++) g_all[80 + k]  = ca_w_in[128 + k];   // wv rows 16..23
    for (int k = 0; k < 64; k++) g_all[144 + k] = ca_w_out[k];
    for (int e = 0; e < 8; e++) {
        float be = ca_b_out[e];
        for (int j = 0; j < 8; j++) be += ca_w_out[e * 8 + j] * ca_b_in[16 + j];
        g_all[208 + e] = be;
    }
}

// ---------------------------------------------------------------------------
// Halving-exchange warp reductions. After return, lane holds fully-reduced
// value(s); for N<=32 index = lane >> log2(32/N).
// ---------------------------------------------------------------------------
template <int N>
__device__ __forceinline__ void warp_fold_reduce(float* V, int lane) {
    int c = N;
#pragma unroll
    for (int o = 16; o >= 1; o >>= 1) {
        if (c > 1) {
            int half = c >> 1;
#pragma unroll
            for (int j = 0; j < half; j++) {
                float send = (lane & o) ? V[j] : V[j + half];
                float recv = __shfl_xor_sync(FULLMASK, send, o);
                V[j] = ((lane & o) ? V[j + half] : V[j]) + recv;
            }
            c = half;
        } else {
            V[0] += __shfl_xor_sync(FULLMASK, V[0], o);
        }
    }
}

template <int N>
__device__ __forceinline__ void warp_fold_reduce2(ull* V, int lane) {
    int c = N;
#pragma unroll
    for (int o = 16; o >= 1; o >>= 1) {
        if (c > 1) {
            int half = c >> 1;
#pragma unroll
            for (int j = 0; j < half; j++) {
                ull send = (lane & o) ? V[j] : V[j + half];
                ull recv = __shfl_xor_sync(FULLMASK, send, o);
                V[j] = add2((lane & o) ? V[j + half] : V[j], recv);
            }
            c = half;
        } else {
            V[0] = add2(V[0], __shfl_xor_sync(FULLMASK, V[0], o));
        }
    }
}

// ---------------------------------------------------------------------------
// Main kernel: one CTA per batch element. 64 threads, 8 tokens per thread,
// x register-resident (loaded once as ull pairs — no packing movs).
// ---------------------------------------------------------------------------
__global__ void __launch_bounds__(64, 10)
afs_main_kernel(const float* __restrict__ x,
                const float* __restrict__ r_w1, const float* __restrict__ r_b1,
                const float* __restrict__ r_w2, const float* __restrict__ r_b2,
                float* __restrict__ out_head, float* __restrict__ out_sim)
{
    const int b = blockIdx.x;
    const int tid = threadIdx.x;
    const int lane = tid & 31;
    const int wid = tid >> 5;

    __shared__ __align__(16) float redA[2][64];   // per-warp A partials
    __shared__ float redS[2][8];                  // per-warp exp-sum partials
    __shared__ __align__(16) float redF[2][32];   // per-warp final-factor partials
    __shared__ float redD[2][4];                  // per-warp sim exp-sum partials
    __shared__ __align__(16) float sQ[32];        // Q_cross [f][e]

    // x tile into registers as packed feature pairs; token t_k = tid + 64*k.
    // ulonglong2 load == two f32x2 pairs bit-identical to pk2(x[2m],x[2m+1]).
    const ulonglong2* X2 = reinterpret_cast<const ulonglong2*>(x + (size_t)b * 4096);
    ull x2[8][4];
#pragma unroll
    for (int t = 0; t < 8; t++) {
        ulonglong2 u0 = __ldcs(&X2[(tid + 64 * t) * 2]);
        ulonglong2 u1 = __ldcs(&X2[(tid + 64 * t) * 2 + 1]);
        x2[t][0] = u0.x; x2[t][1] = u0.y;
        x2[t][2] = u1.x; x2[t][3] = u1.y;
    }

    const ull* cw2 = reinterpret_cast<const ull*>(c_all);   // [p*4+h] pairs; bias at [32+p]

    // --- phase 1: scores -> ex2 -> A partials; p in 4 chunks of 2 ---
#pragma unroll
    for (int c = 0; c < 4; c++) {
        ull A2[8];                                 // [pp*4+h]
#pragma unroll
        for (int j = 0; j < 8; j++) A2[j] = 0ull;
        float sums[2] = {0.f, 0.f};

#pragma unroll
        for (int t = 0; t < 8; t++) {
#pragma unroll
            for (int pp = 0; pp < 2; pp++) {
                int p = 2 * c + pp;
                ull acc = fma2(cw2[p * 4 + 0], x2[t][0],
                          fma2(cw2[p * 4 + 1], x2[t][1],
                          fma2(cw2[p * 4 + 2], x2[t][2],
                          fma2(cw2[p * 4 + 3], x2[t][3], cw2[32 + p]))));
                float slo, shi; upk2(acc, slo, shi);
                float e = ex2(slo + shi);          // bias+log2e prefolded
                sums[pp] += e;
                ull e2 = pk2(e, e);
#pragma unroll
                for (int h = 0; h < 4; h++)
                    A2[pp * 4 + h] = fma2(e2, x2[t][h], A2[pp * 4 + h]);
            }
        }

        warp_fold_reduce2<8>(A2, lane);            // lane holds packed idx lane>>2
        if (!(lane & 3))
            reinterpret_cast<ull*>(&redA[wid][16 * c])[lane >> 2] = A2[0];

        warp_fold_reduce<2>(sums, lane);           // lane holds idx lane>>4
        if (!(lane & 15)) redS[wid][2 * c + (lane >> 4)] = sums[0];
    }

    __syncthreads();

    // --- warp 0: ctx + Q_cross (constant-bank weights, no L1 traffic) ---
    if (wid == 0) {
        int f = lane >> 3, j = lane & 7;       // lane <-> (f, j)
        int h = j >> 2, p = h * 4 + f;
        float At[8];
#pragma unroll
        for (int i = 0; i < 8; i++) At[i] = 0.f;
        float den = 0.f;
#pragma unroll
        for (int w = 0; w < 2; w++) {
            const float4* r4 = reinterpret_cast<const float4*>(&redA[w][p * 8]);
            float4 v0 = r4[0], v1 = r4[1];
            At[0] += v0.x; At[1] += v0.y; At[2] += v0.z; At[3] += v0.w;
            At[4] += v1.x; At[5] += v1.y; At[6] += v1.z; At[7] += v1.w;
            den += redS[w][p];
        }

        float accv = 0.f;
#pragma unroll
        for (int i = 0; i < 8; i++) accv = fmaf(c_all[80 + j * 8 + i], At[i], accv);
        float ctxv = accv / den;                 // v bias folded into b_eff

        float q = c_all[208 + j];                // b_eff[e=j]
#pragma unroll
        for (int jj = 0; jj < 8; jj++) {
            float cv = __shfl_sync(FULLMASK, ctxv, f * 8 + jj);
            q = fmaf(c_all[144 + j * 8 + jj], cv, q);
        }
        sQ[f * 8 + j] = q;
    }
    __syncthreads();

    // --- phase 2: similarity (raw out), exp, FF + denom; f in 2 chunks of 2 ---
    const ull* sQ2 = reinterpret_cast<const ull*>(sQ);   // [f*4+h]
    float* simbase = out_sim + (size_t)b * 2048;
#pragma unroll
    for (int c = 0; c < 2; c++) {
        ull FF2[8];                                      // [ff*4+h]
#pragma unroll
        for (int j = 0; j < 8; j++) FF2[j] = 0ull;
        float ds[2] = {0.f, 0.f};

#pragma unroll
        for (int t = 0; t < 8; t++) {
#pragma unroll
            for (int ff = 0; ff < 2; ff++) {
                int f = 2 * c + ff;
                ull acc = fma2(sQ2[f * 4 + 0], x2[t][0],
                          fma2(sQ2[f * 4 + 1], x2[t][1],
                          fma2(sQ2[f * 4 + 2], x2[t][2],
                          fma2(sQ2[f * 4 + 3], x2[t][3], 0ull))));
                float slo, shi; upk2(acc, slo, shi);
                float s = slo + shi;
                __stcs(&simbase[f * 512 + tid + 64 * t], s);   // pre-softmax sim
                float e = __expf(s);
                ds[ff] += e;
                ull e2 = pk2(e, e);
#pragma unroll
                for (int h = 0; h < 4; h++)
                    FF2[ff * 4 + h] = fma2(e2, x2[t][h], FF2[ff * 4 + h]);
            }
        }

        warp_fold_reduce2<8>(FF2, lane);                 // lane holds packed idx lane>>2
        if (!(lane & 3))
            reinterpret_cast<ull*>(&redF[wid][16 * c])[lane >> 2] = FF2[0];

        warp_fold_reduce<2>(ds, lane);                   // lane holds idx lane>>4
        if (!(lane & 15)) redD[wid][2 * c + (lane >> 4)] = ds[0];
    }

    __syncthreads();

    // --- warp 0: normalize final factors + regression head (coalesced) ---
    if (wid == 0) {
        float s = 0.f;
#pragma unroll
        for (int w = 0; w < 2; w++) s += redF[w][lane];
        int f = lane >> 3;
        float den = 0.f;
#pragma unroll
        for (int w = 0; w < 2; w++) den += redD[w][f];
        float fused = s / den;          // lane k holds fused[k], k = f*8+e

        // hp[h] = r_w1[h][lane] * fused[lane]; coalesced loads, then fold<16>
        float hp[16];
#pragma unroll
        for (int h = 0; h < 16; h++)
            hp[h] = r_w1[h * 32 + lane] * fused;
        warp_fold_reduce<16>(hp, lane);          // lane holds h = lane>>1

        int h = lane >> 1;
        float hv = fmaxf(hp[0] + r_b1[h], 0.f);
        float o = (lane & 1) ? 0.f : hv * r_w2[h];
#pragma unroll
        for (int off = 16; off >= 1; off >>= 1)
            o += __shfl_xor_sync(FULLMASK, o, off);
        if (lane == 0) out_head[b] = o + r_b2[0];
    }
}

// ---------------------------------------------------------------------------
extern "C" void kernel_launch(void* const* d_in, const int* in_sizes, int n_in,
                              void* d_out, int out_size)
{
    const float* x        = (const float*)d_in[0];
    const float* Q        = (const float*)d_in[1];
    const float* sa_w_in  = (const float*)d_in[2];
    const float* sa_b_in  = (const float*)d_in[3];
    const float* sa_w_out = (const float*)d_in[4];
    const float* sa_b_out = (const float*)d_in[5];
    const float* ca_w_in  = (const float*)d_in[6];
    const float* ca_b_in  = (const float*)d_in[7];
    const float* ca_w_out = (const float*)d_in[8];
    const float* ca_b_out = (const float*)d_in[9];
    const float* r_w1     = (const float*)d_in[10];
    const float* r_b1     = (const float*)d_in[11];
    const float* r_w2     = (const float*)d_in[12];
    const float* r_b2     = (const float*)d_in[13];

    int B = in_sizes[0] / (512 * 8);

    float* out = (float*)d_out;
    float* out_head = out;       // (out, similarity) tuple order: out first
    float* out_sim  = out + B;   // then [B, 4, 512] similarity

    precompute_kernel<<<1, 32>>>(Q, sa_w_in, sa_b_in, sa_w_out, sa_b_out,
                                 ca_w_in, ca_b_in, ca_w_out, ca_b_out);

    // copy all folded/packed batch-invariant weights into the constant bank
    void* pAll = nullptr;
    cudaGetSymbolAddress(&pAll, g_all);
    cudaMemcpyToSymbolAsync(c_all, pAll, 216 * sizeof(float), 0,
                            cudaMemcpyDeviceToDevice, 0);

    afs_main_kernel<<<B, 64>>>(x, r_w1, r_b1, r_w2, r_b2, out_head, out_sim);
}